// round 3
// baseline (speedup 1.0000x reference)
#include <cuda_runtime.h>
#include <math.h>

// Problem constants (PerturbationAttention): delta [B, C, D] fp32, k = 256
#define B_DIM 2048
#define C_DIM 512
#define D_DIM 256
#define K_SEL 256

// Scratch (no allocations allowed): sigma buffer (4 MB) + global max bits.
__device__ float        g_sigma[B_DIM * C_DIM];
__device__ unsigned int g_max_bits;

// ---------------------------------------------------------------------------
// Kernel 0: reset the global max (must be re-done every launch: deterministic)
// ---------------------------------------------------------------------------
__global__ void pa_init_kernel() { g_max_bits = 0u; }

// ---------------------------------------------------------------------------
// Kernel 1: sigma[r] = ||delta[r, :]||_2 for r in [0, B*C), plus global max.
// Warp-per-row: each lane loads 2 float4 (32 B) -> 1 KiB per warp per row,
// fully coalesced. Grid-stride over rows; one atomicMax per block.
// ---------------------------------------------------------------------------
__global__ void __launch_bounds__(512, 2)
pa_sigma_kernel(const float* __restrict__ delta)
{
    const int lane = threadIdx.x & 31;
    const int wid  = threadIdx.x >> 5;              // 0..15
    const int warps_per_block = 512 / 32;           // 16
    const int gwarp = blockIdx.x * warps_per_block + wid;
    const int warp_stride = gridDim.x * warps_per_block;

    float lmax = 0.0f;

    for (int row = gwarp; row < B_DIM * C_DIM; row += warp_stride) {
        const float4* p = reinterpret_cast<const float4*>(delta + (size_t)row * D_DIM);
        float4 a = p[lane];        // elements [lane*4 .. lane*4+3]       (first 512 B)
        float4 b = p[lane + 32];   // elements [128 + lane*4 .. +3]       (second 512 B)
        float s = a.x * a.x + a.y * a.y + a.z * a.z + a.w * a.w
                + b.x * b.x + b.y * b.y + b.z * b.z + b.w * b.w;

        #pragma unroll
        for (int o = 16; o > 0; o >>= 1)
            s += __shfl_xor_sync(0xffffffffu, s, o);

        float sig = sqrtf(s);                       // same value in all lanes
        if (lane == 0) g_sigma[row] = sig;
        lmax = fmaxf(lmax, sig);
    }

    // Block-level max, then a single global atomic per block.
    __shared__ float smax[16];
    if (lane == 0) smax[wid] = lmax;
    __syncthreads();
    if (wid == 0) {
        float v = (lane < warps_per_block) ? smax[lane] : 0.0f;
        #pragma unroll
        for (int o = 8; o > 0; o >>= 1)
            v = fmaxf(v, __shfl_xor_sync(0xffffffffu, v, o));
        if (lane == 0)
            atomicMax(&g_max_bits, __float_as_uint(v));  // sigma >= 0: uint order == float order
    }
}

// ---------------------------------------------------------------------------
// Kernel 2: per batch-row b (one block of C_DIM=512 threads):
//   t   = tanh(1 - sigma / gmax)
//   att = softmax_C(t)
//   zero the K_SEL smallest att values (ties -> lowest index), write out.
// Selection: 4-pass 8-bit radix select on float bit patterns (all positive).
// ---------------------------------------------------------------------------
__global__ void __launch_bounds__(512, 2)
pa_select_kernel(float* __restrict__ out)
{
    const int b = blockIdx.x;
    const int i = threadIdx.x;          // 0..511 == column index
    const int lane = i & 31;
    const int w    = i >> 5;            // warp id 0..15

    __shared__ float    s_red[16];
    __shared__ unsigned s_hist[256];
    __shared__ unsigned s_bin, s_excl;
    __shared__ int      s_wcnt[16];

    const float gmax = __uint_as_float(g_max_bits);
    const float sig  = g_sigma[b * C_DIM + i];
    const float t    = tanhf(1.0f - sig / gmax);

    // ---- block max of t (softmax stabilization) ----
    float m = t;
    #pragma unroll
    for (int o = 16; o > 0; o >>= 1)
        m = fmaxf(m, __shfl_xor_sync(0xffffffffu, m, o));
    if (lane == 0) s_red[w] = m;
    __syncthreads();
    {
        float v = s_red[lane & 15];
        #pragma unroll
        for (int o = 8; o > 0; o >>= 1)
            v = fmaxf(v, __shfl_xor_sync(0xffffffffu, v, o));
        m = v;  // every thread computes the same block max via its own warp
    }
    __syncthreads();

    const float e = expf(t - m);

    // ---- block sum of e ----
    float s = e;
    #pragma unroll
    for (int o = 16; o > 0; o >>= 1)
        s += __shfl_xor_sync(0xffffffffu, s, o);
    if (lane == 0) s_red[w] = s;
    __syncthreads();
    {
        float v = s_red[lane & 15];
        #pragma unroll
        for (int o = 8; o > 0; o >>= 1)
            v += __shfl_xor_sync(0xffffffffu, v, o);
        s = v;
    }

    const float att = e / s;
    const unsigned key = __float_as_uint(att);   // att > 0: bit order == value order

    // ---- radix select: find k-th smallest key (k = K_SEL) ----
    unsigned prefix = 0u;       // high bits of the k-th smallest, resolved so far
    unsigned krem   = K_SEL;    // rank remaining within the current bucket

    #pragma unroll
    for (int shift = 24; shift >= 0; shift -= 8) {
        if (i < 256) s_hist[i] = 0u;
        __syncthreads();

        const bool in_bucket = (shift == 24) || ((key >> (shift + 8)) == prefix);
        if (in_bucket) atomicAdd(&s_hist[(key >> shift) & 255u], 1u);
        __syncthreads();

        // inclusive scan over 256 bins (Hillis–Steele, all threads hit syncs)
        #pragma unroll
        for (int off = 1; off < 256; off <<= 1) {
            unsigned v = 0u;
            if (i < 256 && i >= off) v = s_hist[i - off];
            __syncthreads();
            if (i < 256) s_hist[i] += v;
            __syncthreads();
        }

        // the bin containing rank 'krem' (1-based): smallest i with incl[i] >= krem
        if (i < 256) {
            unsigned incl = s_hist[i];
            unsigned excl = (i == 0) ? 0u : s_hist[i - 1];
            if (incl >= krem && excl < krem) { s_bin = (unsigned)i; s_excl = excl; }
        }
        __syncthreads();

        prefix = (prefix << 8) | s_bin;
        krem  -= s_excl;
        __syncthreads();
    }

    const unsigned T = prefix;          // exact bits of the k-th smallest att
    const unsigned tie_budget = krem;   // how many values == T get zeroed (lowest idx first)

    // ---- tie rank: index-ordered prefix count of (key == T) ----
    const bool eq = (key == T);
    const unsigned bal = __ballot_sync(0xffffffffu, eq);
    if (lane == 0) s_wcnt[w] = __popc(bal);
    __syncthreads();
    int woff = 0;
    #pragma unroll
    for (int j = 0; j < 16; j++)
        if (j < w) woff += s_wcnt[j];
    const unsigned tie_rank = (unsigned)woff + (unsigned)__popc(bal & ((1u << lane) - 1u));

    const bool zero = (key < T) || (eq && tie_rank < tie_budget);
    out[b * C_DIM + i] = zero ? 0.0f : att;
}

// ---------------------------------------------------------------------------
// Launch
// ---------------------------------------------------------------------------
extern "C" void kernel_launch(void* const* d_in, const int* in_sizes, int n_in,
                              void* d_out, int out_size)
{
    const float* delta = (const float*)d_in[0];
    float* out = (float*)d_out;
    (void)in_sizes; (void)n_in; (void)out_size;   // shapes fixed for this problem

    pa_init_kernel<<<1, 1>>>();
    pa_sigma_kernel<<<4096, 512>>>(delta);        // 65536 warps, 16 rows each (grid-stride)
    pa_select_kernel<<<B_DIM, C_DIM>>>(out);
}